// round 2
// baseline (speedup 1.0000x reference)
#include <cuda_runtime.h>

#define NB 65536
typedef unsigned long long ull;

// ---------------- device scratch (allocation-free) ----------------
__device__ int   g_cnt[16];                 // [node][expert] counts
__device__ int   g_gidx[16][NB];            // per (node,expert) row ids
__device__ float g_h[(size_t)NB * 256];     // hidden buffer
__device__ float g_bufA[(size_t)NB * 384];  // concat ping  (cols 0:128 prev, 128:384 pre)
__device__ float g_bufB[(size_t)NB * 384];  // concat pong

// ---------------- f32x2 helpers ----------------
__device__ __forceinline__ ull pk2(float x, float y) {
    ull r; asm("mov.b64 %0,{%1,%2};" : "=l"(r) : "f"(x), "f"(y)); return r;
}
__device__ __forceinline__ float2 upk2(ull v) {
    float2 f; asm("mov.b64 {%0,%1},%2;" : "=f"(f.x), "=f"(f.y) : "l"(v)); return f;
}
__device__ __forceinline__ void fma2(ull& d, ull a, ull b) {
    asm("fma.rn.f32x2 %0,%1,%2,%0;" : "+l"(d) : "l"(a), "l"(b));
}

// ---------------- routing ----------------
__global__ void k_zero() { if (threadIdx.x < 16) g_cnt[threadIdx.x] = 0; }

__global__ void k_route(const float* __restrict__ in) {
    int row = blockIdx.x * 256 + threadIdx.x;
    if (row >= NB) return;
    int lane = threadIdx.x & 31;
    const float* oh = in + (size_t)row * 144 + 128;
    #pragma unroll
    for (int j = 0; j < 4; j++) {
        int e = 0;
        #pragma unroll
        for (int t = 1; t < 4; t++) if (oh[j * 4 + t] > 0.5f) e = t;
        #pragma unroll
        for (int ee = 0; ee < 4; ee++) {
            unsigned m = __ballot_sync(0xffffffffu, e == ee);
            if (e == ee) {
                int leader = __ffs(m) - 1, base = 0;
                if (lane == leader) base = atomicAdd(&g_cnt[j * 4 + ee], __popc(m));
                base = __shfl_sync(m, base, leader);
                g_gidx[j * 4 + ee][base + __popc(m & ((1u << lane) - 1u))] = row;
            }
        }
    }
}

// ---------------- buffer selectors ----------------
__device__ __forceinline__ const float* selsrc(int s, const float* in) {
    if (s == 0) return in;
    if (s == 1) return g_h;
    if (s == 2) return g_bufA;
    return g_bufB;
}
__device__ __forceinline__ float* seldst(int s) {
    if (s == 1) return g_h;
    if (s == 2) return g_bufA;
    return g_bufB;
}

// ---------------- grouped GEMM: relu(A[gathered] @ W[e] + b[e]) scatter ----------------
// Tile: 128 rows x 64 cols per block (blockIdx.y = 64-col block), BK=32, 256 threads.
// Thread micro-tile: 8 rows (4 packed pairs) x 4 cols, FFMA2 accumulation.
template<int IN, int OUT, bool RELU>
__global__ __launch_bounds__(256) void k_gemm(
        int node, int asel, const float* __restrict__ hin, int lda, int acol,
        const float* __restrict__ Wall, const float* __restrict__ Ball,
        int csel, int ldc, int ccol)
{
    __shared__ float As[32][132];     // transposed [k][row], stride 132 (16B-divisible)
    __shared__ ull   Ws2[32][64];     // duplicated (w,w) pairs
    __shared__ int   s_ridx[128];

    // map blockIdx.x -> (expert, tile)
    int e = -1, tile = 0, n = 0, acc = 0;
    #pragma unroll
    for (int ee = 0; ee < 4; ee++) {
        int ne = g_cnt[node * 4 + ee];
        int nt = (ne + 127) >> 7;
        if (e < 0 && (int)blockIdx.x < acc + nt) { e = ee; tile = (int)blockIdx.x - acc; n = ne; }
        acc += nt;
    }
    if (e < 0) return;

    const float* A = selsrc(asel, hin);
    float*       C = seldst(csel);
    const float* W = Wall + (size_t)e * IN * OUT;
    const int cb  = blockIdx.y;
    const int tid = threadIdx.x;

    if (tid < 128) {
        int r = tile * 128 + tid;
        s_ridx[tid] = (r < n) ? g_gidx[node * 4 + e][r] : -1;
    }
    __syncthreads();

    const int row0 = (tid >> 4) * 8;
    const int col0 = (tid & 15) * 4;
    ull accv[4][4];
    #pragma unroll
    for (int i = 0; i < 4; i++)
        #pragma unroll
        for (int j = 0; j < 4; j++) accv[i][j] = 0ull;

    for (int kk = 0; kk < IN; kk += 32) {
        // stage A tile (transposed), zeros for padding rows
        #pragma unroll
        for (int j = 0; j < 4; j++) {
            int i = tid + j * 256, r = i >> 3, f = i & 7;
            int ri = s_ridx[r];
            float4 v = make_float4(0.f, 0.f, 0.f, 0.f);
            if (ri >= 0) v = *(const float4*)(A + (size_t)ri * lda + acol + kk + f * 4);
            As[f * 4 + 0][r] = v.x; As[f * 4 + 1][r] = v.y;
            As[f * 4 + 2][r] = v.z; As[f * 4 + 3][r] = v.w;
        }
        // stage W chunk as duplicated pairs
        #pragma unroll
        for (int j = 0; j < 8; j++) {
            int i = tid + j * 256, k = i >> 6, c = i & 63;
            float w = W[(size_t)(kk + k) * OUT + cb * 64 + c];
            Ws2[k][c] = pk2(w, w);
        }
        __syncthreads();
        #pragma unroll
        for (int k = 0; k < 32; k++) {
            const ull* ap = (const ull*)&As[k][row0];
            ull a0 = ap[0], a1 = ap[1], a2 = ap[2], a3 = ap[3];
            const ull* wp = &Ws2[k][col0];
            ull w0 = wp[0], w1 = wp[1], w2 = wp[2], w3 = wp[3];
            fma2(accv[0][0], a0, w0); fma2(accv[0][1], a0, w1); fma2(accv[0][2], a0, w2); fma2(accv[0][3], a0, w3);
            fma2(accv[1][0], a1, w0); fma2(accv[1][1], a1, w1); fma2(accv[1][2], a1, w2); fma2(accv[1][3], a1, w3);
            fma2(accv[2][0], a2, w0); fma2(accv[2][1], a2, w1); fma2(accv[2][2], a2, w2); fma2(accv[2][3], a2, w3);
            fma2(accv[3][0], a3, w0); fma2(accv[3][1], a3, w1); fma2(accv[3][2], a3, w2); fma2(accv[3][3], a3, w3);
        }
        __syncthreads();
    }

    int cg = cb * 64 + col0;
    float4 bv = *(const float4*)(Ball + (size_t)e * OUT + cg);
    #pragma unroll
    for (int p = 0; p < 4; p++) {
        float2 c0 = upk2(accv[p][0]), c1 = upk2(accv[p][1]);
        float2 c2 = upk2(accv[p][2]), c3 = upk2(accv[p][3]);
        float4 o0 = make_float4(c0.x + bv.x, c1.x + bv.y, c2.x + bv.z, c3.x + bv.w);
        float4 o1 = make_float4(c0.y + bv.x, c1.y + bv.y, c2.y + bv.z, c3.y + bv.w);
        if (RELU) {
            o0.x = fmaxf(o0.x, 0.f); o0.y = fmaxf(o0.y, 0.f); o0.z = fmaxf(o0.z, 0.f); o0.w = fmaxf(o0.w, 0.f);
            o1.x = fmaxf(o1.x, 0.f); o1.y = fmaxf(o1.y, 0.f); o1.z = fmaxf(o1.z, 0.f); o1.w = fmaxf(o1.w, 0.f);
        }
        int r0 = row0 + 2 * p;
        int ri0 = s_ridx[r0], ri1 = s_ridx[r0 + 1];
        if (ri0 >= 0) *(float4*)(C + (size_t)ri0 * ldc + ccol + cg) = o0;
        if (ri1 >= 0) *(float4*)(C + (size_t)ri1 * ldc + ccol + cg) = o1;
    }
}

// ---------------- final 256->8 head (no relu) ----------------
__global__ __launch_bounds__(256) void k_final(
        const float* __restrict__ in, const float* __restrict__ W,
        const float* __restrict__ Bb, float* __restrict__ out)
{
    int gw   = (blockIdx.x * 256 + threadIdx.x) >> 5;   // one warp per row
    int lane = threadIdx.x & 31;
    if (gw >= NB) return;
    const float* oh = in + (size_t)gw * 144 + 140;      // node-3 one-hot
    int e = 0;
    #pragma unroll
    for (int t = 1; t < 4; t++) if (oh[t] > 0.5f) e = t;
    const float* h = g_h + (size_t)gw * 256;
    const float* w = W + (size_t)e * 2048;
    float acc[8] = {0, 0, 0, 0, 0, 0, 0, 0};
    #pragma unroll
    for (int kk = 0; kk < 256; kk += 32) {
        int k = kk + lane;
        float hv = h[k];
        float4 wa = *(const float4*)(w + k * 8);
        float4 wb = *(const float4*)(w + k * 8 + 4);
        acc[0] += hv * wa.x; acc[1] += hv * wa.y; acc[2] += hv * wa.z; acc[3] += hv * wa.w;
        acc[4] += hv * wb.x; acc[5] += hv * wb.y; acc[6] += hv * wb.z; acc[7] += hv * wb.w;
    }
    #pragma unroll
    for (int o = 16; o > 0; o >>= 1)
        #pragma unroll
        for (int c = 0; c < 8; c++) acc[c] += __shfl_xor_sync(0xffffffffu, acc[c], o);
    if (lane < 8) {
        float v = acc[0];
        switch (lane) {
            case 1: v = acc[1]; break; case 2: v = acc[2]; break;
            case 3: v = acc[3]; break; case 4: v = acc[4]; break;
            case 5: v = acc[5]; break; case 6: v = acc[6]; break;
            case 7: v = acc[7]; break; default: break;
        }
        out[(size_t)gw * 8 + lane] = v + Bb[e * 8 + lane];
    }
}

// ---------------- launch ----------------
extern "C" void kernel_launch(void* const* d_in, const int* in_sizes, int n_in,
                              void* d_out, int out_size) {
    const float* in = (const float*)d_in[0];
    float* out = (float*)d_out;
    auto P = [&](int i) { return (const float*)d_in[i]; };

    k_zero<<<1, 16>>>();
    k_route<<<NB / 256, 256>>>(in);

    dim3 g4(516, 4), g2(516, 2);
    // node 0: x0(32)->256 relu -> g_h ; g_h 256->128 relu -> bufA[0:128]
    k_gemm<32, 256, true><<<g4, 256>>>(0, 0, in, 144, 0,   P(1),  P(2),  1, 256, 0);
    k_gemm<256, 128, true><<<g2, 256>>>(0, 1, in, 256, 0,  P(3),  P(4),  2, 384, 0);
    // node 1: pre x1(32)->256 relu -> bufA[128:384] ; bufA 384->256 relu -> g_h ; 256->128 -> bufB[0:128]
    k_gemm<32, 256, true><<<g4, 256>>>(1, 0, in, 144, 32,  P(5),  P(6),  2, 384, 128);
    k_gemm<384, 256, true><<<g4, 256>>>(1, 2, in, 384, 0,  P(7),  P(8),  1, 256, 0);
    k_gemm<256, 128, true><<<g2, 256>>>(1, 1, in, 256, 0,  P(9),  P(10), 3, 384, 0);
    // node 2
    k_gemm<32, 256, true><<<g4, 256>>>(2, 0, in, 144, 64,  P(11), P(12), 3, 384, 128);
    k_gemm<384, 256, true><<<g4, 256>>>(2, 3, in, 384, 0,  P(13), P(14), 1, 256, 0);
    k_gemm<256, 128, true><<<g2, 256>>>(2, 1, in, 256, 0,  P(15), P(16), 2, 384, 0);
    // node 3
    k_gemm<32, 256, true><<<g4, 256>>>(3, 0, in, 144, 96,  P(17), P(18), 2, 384, 128);
    k_gemm<384, 256, true><<<g4, 256>>>(3, 2, in, 384, 0,  P(19), P(20), 1, 256, 0);
    k_final<<<NB / 8, 256>>>(in, P(21), P(22), out);
}

// round 4
// speedup vs baseline: 3.0167x; 3.0167x over previous
#include <cuda_runtime.h>
#include <cuda_fp16.h>
#include <cstdint>

#define NB 65536

// ============================ device scratch ============================
__device__ int g_cnt[16];
__device__ int g_gidx[16][NB];
__device__ __align__(16) float g_h[(size_t)NB * 256];
__device__ __align__(16) float g_bufA[(size_t)NB * 384];
__device__ __align__(16) float g_bufB[(size_t)NB * 384];
// fp16 hi/lo weight planes, n-major [e][n][k], hi plane then lo plane per layer
__device__ __align__(16) __half g_wprep[3407872];

// layer offsets into g_wprep (half units)
static const size_t OFF_W0_0 = 0;
static const size_t OFF_W0_1 = 65536;
static const size_t OFF_W1p  = 327680;
static const size_t OFF_W1_0 = 393216;
static const size_t OFF_W1_1 = 1179648;
static const size_t OFF_W2p  = 1441792;
static const size_t OFF_W2_0 = 1507328;
static const size_t OFF_W2_1 = 2293760;
static const size_t OFF_W3p  = 2555904;
static const size_t OFF_W3_0 = 2621440;

// ============================ routing ============================
__global__ void k_zero() { if (threadIdx.x < 16) g_cnt[threadIdx.x] = 0; }

__global__ void k_route(const float* __restrict__ in) {
    int row = blockIdx.x * 256 + threadIdx.x;
    if (row >= NB) return;
    int lane = threadIdx.x & 31;
    const float* oh = in + (size_t)row * 144 + 128;
    #pragma unroll
    for (int j = 0; j < 4; j++) {
        int e = 0;
        #pragma unroll
        for (int t = 1; t < 4; t++) if (oh[j * 4 + t] > 0.5f) e = t;
        #pragma unroll
        for (int ee = 0; ee < 4; ee++) {
            unsigned m = __ballot_sync(0xffffffffu, e == ee);
            if (e == ee) {
                int leader = __ffs(m) - 1, base = 0;
                if (lane == leader) base = atomicAdd(&g_cnt[j * 4 + ee], __popc(m));
                base = __shfl_sync(m, base, leader);
                g_gidx[j * 4 + ee][base + __popc(m & ((1u << lane) - 1u))] = row;
            }
        }
    }
}

// ============================ weight prep ============================
// W [E][IN][OUT] fp32 -> hi/lo fp16 planes, n-major: plane[(e*OUT+n)*IN + k]
__global__ void k_prep(const float* __restrict__ W, int IN, int OUT, size_t base) {
    int total = 4 * OUT * IN;
    for (int id = blockIdx.x * 256 + threadIdx.x; id < total; id += gridDim.x * 256) {
        int e = id / (OUT * IN);
        int rem = id % (OUT * IN);
        int n = rem / IN, k = rem % IN;
        float v = W[((size_t)e * IN + k) * OUT + n];
        __half h = __float2half_rn(v);
        __half l = __float2half_rn(v - __half2float(h));
        size_t o = (size_t)(e * OUT + n) * IN + k;
        g_wprep[base + o] = h;
        g_wprep[base + (size_t)4 * OUT * IN + o] = l;
    }
}

// ============================ mma helper ============================
#define MMA16816(c, a, b) \
    asm volatile("mma.sync.aligned.m16n8k16.row.col.f32.f16.f16.f32 " \
        "{%0,%1,%2,%3}, {%4,%5,%6,%7}, {%8,%9}, {%0,%1,%2,%3};" \
        : "+f"((c)[0]), "+f"((c)[1]), "+f"((c)[2]), "+f"((c)[3]) \
        : "r"((a)[0]), "r"((a)[1]), "r"((a)[2]), "r"((a)[3]), \
          "r"((b)[0]), "r"((b)[1]))

// ============================ tensor GEMM ============================
// Block: 128 gathered rows x 128 cols (blockIdx.y = col block).
// K-extended split: A chunk cols [Ah | Al | Ah], B chunk cols [Bh | Bh | Bl]
// => fp32-accurate product via 3 fused fp16 passes. BK=32 -> 96 ext cols.
template <int IN, int OUT>
__global__ __launch_bounds__(256) void k_tgemm(
        int node, int asel, int acol, const float* __restrict__ fin,
        size_t woff, const float* __restrict__ Ball,
        int csel, int ldc, int ccol) {
    constexpr int SA = 104;          // padded row stride (halfs); 52 words, conflict-free
    constexpr int NCH = IN / 32;

    extern __shared__ __half dyn[];
    __half* sA = dyn;                // 128 x 104
    __half* sB = dyn + 128 * SA;     // 128 x 104
    __shared__ int s_ridx[128];
    __shared__ float s_bias[128];

    const int tid = threadIdx.x;
    const int cb = blockIdx.y;

    // map blockIdx.x -> (expert, tile)
    int e = -1, tile = 0, nrows = 0, acc0 = 0;
    #pragma unroll
    for (int ee = 0; ee < 4; ee++) {
        int ne = g_cnt[node * 4 + ee];
        int nt = (ne + 127) >> 7;
        if (e < 0 && (int)blockIdx.x < acc0 + nt) { e = ee; tile = (int)blockIdx.x - acc0; nrows = ne; }
        acc0 += nt;
    }
    if (e < 0) return;

    if (tid < 128) {
        int r = tile * 128 + tid;
        s_ridx[tid] = (r < nrows) ? g_gidx[node * 4 + e][r] : -1;
        s_bias[tid] = Ball[(size_t)e * OUT + cb * 128 + tid];
    }
    __syncthreads();

    const float* Aptr; int lda;
    if (asel == 0)      { Aptr = fin;    lda = 144; }
    else if (asel == 1) { Aptr = g_h;    lda = 256; }
    else if (asel == 2) { Aptr = g_bufA; lda = 384; }
    else                { Aptr = g_bufB; lda = 384; }
    float* C = (csel == 1) ? g_h : (csel == 2 ? g_bufA : g_bufB);

    const __half* wh = g_wprep + woff;
    const __half* wl = wh + (size_t)4 * OUT * IN;

    // staging assignment: thread -> row ar (0..127), half-chunk ak0 (0 or 16)
    const int ar = tid >> 1, ak0 = (tid & 1) * 16;
    const int ari = s_ridx[ar];
    const float* abase = Aptr + (size_t)(ari < 0 ? 0 : ari) * lda + acol + ak0;
    const __half* bhb = wh + ((size_t)(e * OUT + cb * 128 + ar) * IN + ak0);
    const __half* blb = wl + ((size_t)(e * OUT + cb * 128 + ar) * IN + ak0);

    float4 fA[4];
    uint4 bh[2], bl[2];

    auto ldA = [&](int kk) {
        if (ari >= 0) {
            const float4* p = (const float4*)(abase + kk);
            fA[0] = p[0]; fA[1] = p[1]; fA[2] = p[2]; fA[3] = p[3];
        } else {
            fA[0] = fA[1] = fA[2] = fA[3] = make_float4(0.f, 0.f, 0.f, 0.f);
        }
    };
    auto ldB = [&](int kk) {
        const uint4* ph = (const uint4*)(bhb + kk);
        const uint4* pl = (const uint4*)(blb + kk);
        bh[0] = ph[0]; bh[1] = ph[1]; bl[0] = pl[0]; bl[1] = pl[1];
    };
    auto stA = [&]() {
        float v[16] = { fA[0].x, fA[0].y, fA[0].z, fA[0].w,
                        fA[1].x, fA[1].y, fA[1].z, fA[1].w,
                        fA[2].x, fA[2].y, fA[2].z, fA[2].w,
                        fA[3].x, fA[3].y, fA[3].z, fA[3].w };
        unsigned H[8], L[8];
        #pragma unroll
        for (int p = 0; p < 8; p++) {
            float v0 = v[2 * p], v1 = v[2 * p + 1];
            __half h0 = __float2half_rn(v0), h1 = __float2half_rn(v1);
            __half l0 = __float2half_rn(v0 - __half2float(h0));
            __half l1 = __float2half_rn(v1 - __half2float(h1));
            H[p] = ((unsigned)__half_as_ushort(h1) << 16) | __half_as_ushort(h0);
            L[p] = ((unsigned)__half_as_ushort(l1) << 16) | __half_as_ushort(l0);
        }
        uint4 h0 = make_uint4(H[0], H[1], H[2], H[3]);
        uint4 h1 = make_uint4(H[4], H[5], H[6], H[7]);
        uint4 l0 = make_uint4(L[0], L[1], L[2], L[3]);
        uint4 l1 = make_uint4(L[4], L[5], L[6], L[7]);
        __half* r = sA + ar * SA;
        *(uint4*)(r + ak0)          = h0; *(uint4*)(r + ak0 + 8)      = h1;   // Ah
        *(uint4*)(r + 32 + ak0)     = l0; *(uint4*)(r + 32 + ak0 + 8) = l1;   // Al
        *(uint4*)(r + 64 + ak0)     = h0; *(uint4*)(r + 64 + ak0 + 8) = h1;   // Ah
    };
    auto stB = [&]() {
        __half* r = sB + ar * SA;
        *(uint4*)(r + ak0)          = bh[0]; *(uint4*)(r + ak0 + 8)      = bh[1]; // Bh
        *(uint4*)(r + 32 + ak0)     = bh[0]; *(uint4*)(r + 32 + ak0 + 8) = bh[1]; // Bh
        *(uint4*)(r + 64 + ak0)     = bl[0]; *(uint4*)(r + 64 + ak0 + 8) = bl[1]; // Bl
    };

    // warp layout: 4 (m) x 2 (n); warp tile 32 rows x 64 cols
    const int w = tid >> 5, lane = tid & 31;
    const int m0 = (w >> 1) * 32, n0 = (w & 1) * 64;
    const int g = lane >> 2, t4 = lane & 3;

    float acc[2][8][4];
    #pragma unroll
    for (int i = 0; i < 2; i++)
        #pragma unroll
        for (int j = 0; j < 8; j++)
            #pragma unroll
            for (int c = 0; c < 4; c++) acc[i][j][c] = 0.f;

    ldA(0); ldB(0);
    for (int ch = 0; ch < NCH; ch++) {
        stA(); stB();
        if (ch + 1 < NCH) { ldA((ch + 1) * 32); ldB((ch + 1) * 32); }
        __syncthreads();
        #pragma unroll
        for (int ks = 0; ks < 6; ks++) {
            const int kb = ks * 16;
            unsigned a[2][4], b[8][2];
            #pragma unroll
            for (int ms = 0; ms < 2; ms++) {
                const __half* pr = sA + (m0 + ms * 16 + g) * SA + kb + 2 * t4;
                a[ms][0] = *(const unsigned*)pr;
                a[ms][1] = *(const unsigned*)(pr + 8 * SA);
                a[ms][2] = *(const unsigned*)(pr + 8);
                a[ms][3] = *(const unsigned*)(pr + 8 * SA + 8);
            }
            #pragma unroll
            for (int ns = 0; ns < 8; ns++) {
                const __half* pr = sB + (n0 + ns * 8 + g) * SA + kb + 2 * t4;
                b[ns][0] = *(const unsigned*)pr;
                b[ns][1] = *(const unsigned*)(pr + 8);
            }
            #pragma unroll
            for (int ms = 0; ms < 2; ms++)
                #pragma unroll
                for (int ns = 0; ns < 8; ns++)
                    MMA16816(acc[ms][ns], a[ms], b[ns]);
        }
        __syncthreads();
    }

    // epilogue: bias + relu, scatter fp32
    #pragma unroll
    for (int ms = 0; ms < 2; ms++) {
        int r0 = m0 + ms * 16 + g;
        int ri = s_ridx[r0], rj = s_ridx[r0 + 8];
        float* c0p = C + (size_t)(ri < 0 ? 0 : ri) * ldc + ccol + cb * 128;
        float* c1p = C + (size_t)(rj < 0 ? 0 : rj) * ldc + ccol + cb * 128;
        #pragma unroll
        for (int ns = 0; ns < 8; ns++) {
            int cc = n0 + ns * 8 + 2 * t4;
            float b0 = s_bias[cc], b1 = s_bias[cc + 1];
            if (ri >= 0) {
                float2 v = make_float2(fmaxf(acc[ms][ns][0] + b0, 0.f),
                                       fmaxf(acc[ms][ns][1] + b1, 0.f));
                *(float2*)(c0p + cc) = v;
            }
            if (rj >= 0) {
                float2 v = make_float2(fmaxf(acc[ms][ns][2] + b0, 0.f),
                                       fmaxf(acc[ms][ns][3] + b1, 0.f));
                *(float2*)(c1p + cc) = v;
            }
        }
    }
}

// ============================ final 256->8 head (no relu) ============================
__global__ __launch_bounds__(256) void k_final(
        const float* __restrict__ in, const float* __restrict__ W,
        const float* __restrict__ Bb, float* __restrict__ out) {
    int gw = (blockIdx.x * 256 + threadIdx.x) >> 5;
    int lane = threadIdx.x & 31;
    if (gw >= NB) return;
    const float* oh = in + (size_t)gw * 144 + 140;
    int e = 0;
    #pragma unroll
    for (int t = 1; t < 4; t++) if (oh[t] > 0.5f) e = t;
    const float* h = g_h + (size_t)gw * 256;
    const float* w = W + (size_t)e * 2048;
    float acc[8] = {0, 0, 0, 0, 0, 0, 0, 0};
    #pragma unroll
    for (int kk = 0; kk < 256; kk += 32) {
        int k = kk + lane;
        float hv = h[k];
        float4 wa = *(const float4*)(w + k * 8);
        float4 wb = *(const float4*)(w + k * 8 + 4);
        acc[0] += hv * wa.x; acc[1] += hv * wa.y; acc[2] += hv * wa.z; acc[3] += hv * wa.w;
        acc[4] += hv * wb.x; acc[5] += hv * wb.y; acc[6] += hv * wb.z; acc[7] += hv * wb.w;
    }
    #pragma unroll
    for (int o = 16; o > 0; o >>= 1)
        #pragma unroll
        for (int c = 0; c < 8; c++) acc[c] += __shfl_xor_sync(0xffffffffu, acc[c], o);
    if (lane < 8) {
        float v = acc[0];
        switch (lane) {
            case 1: v = acc[1]; break; case 2: v = acc[2]; break;
            case 3: v = acc[3]; break; case 4: v = acc[4]; break;
            case 5: v = acc[5]; break; case 6: v = acc[6]; break;
            case 7: v = acc[7]; break; default: break;
        }
        out[(size_t)gw * 8 + lane] = v + Bb[e * 8 + lane];
    }
}

// ============================ launch ============================
extern "C" void kernel_launch(void* const* d_in, const int* in_sizes, int n_in,
                              void* d_out, int out_size) {
    const float* in = (const float*)d_in[0];
    float* out = (float*)d_out;
    auto P = [&](int i) { return (const float*)d_in[i]; };

    const int DSM = 256 * 104 * 2;  // 53248 B
    cudaFuncSetAttribute((const void*)k_tgemm<32, 256>,
                         cudaFuncAttributeMaxDynamicSharedMemorySize, DSM);
    cudaFuncSetAttribute((const void*)k_tgemm<256, 128>,
                         cudaFuncAttributeMaxDynamicSharedMemorySize, DSM);
    cudaFuncSetAttribute((const void*)k_tgemm<384, 256>,
                         cudaFuncAttributeMaxDynamicSharedMemorySize, DSM);

    auto prep = [&](const float* W, int IN, int OUT, size_t base) {
        int total = 4 * OUT * IN;
        k_prep<<<(total + 255) / 256, 256>>>(W, IN, OUT, base);
    };
    prep(P(1),  32,  256, OFF_W0_0);
    prep(P(3),  256, 128, OFF_W0_1);
    prep(P(5),  32,  256, OFF_W1p);
    prep(P(7),  384, 256, OFF_W1_0);
    prep(P(9),  256, 128, OFF_W1_1);
    prep(P(11), 32,  256, OFF_W2p);
    prep(P(13), 384, 256, OFF_W2_0);
    prep(P(15), 256, 128, OFF_W2_1);
    prep(P(17), 32,  256, OFF_W3p);
    prep(P(19), 384, 256, OFF_W3_0);

    k_zero<<<1, 16>>>();
    k_route<<<NB / 256, 256>>>(in);

    dim3 g2(516, 2), g1(516, 1);
    // node 0
    k_tgemm<32, 256><<<g2, 256, DSM>>>(0, 0, 0,  in, OFF_W0_0, P(2),  1, 256, 0);
    k_tgemm<256, 128><<<g1, 256, DSM>>>(0, 1, 0,  in, OFF_W0_1, P(4),  2, 384, 0);
    // node 1
    k_tgemm<32, 256><<<g2, 256, DSM>>>(1, 0, 32, in, OFF_W1p,  P(6),  2, 384, 128);
    k_tgemm<384, 256><<<g2, 256, DSM>>>(1, 2, 0,  in, OFF_W1_0, P(8),  1, 256, 0);
    k_tgemm<256, 128><<<g1, 256, DSM>>>(1, 1, 0,  in, OFF_W1_1, P(10), 3, 384, 0);
    // node 2
    k_tgemm<32, 256><<<g2, 256, DSM>>>(2, 0, 64, in, OFF_W2p,  P(12), 3, 384, 128);
    k_tgemm<384, 256><<<g2, 256, DSM>>>(2, 3, 0,  in, OFF_W2_0, P(14), 1, 256, 0);
    k_tgemm<256, 128><<<g1, 256, DSM>>>(2, 1, 0,  in, OFF_W2_1, P(16), 2, 384, 0);
    // node 3
    k_tgemm<32, 256><<<g2, 256, DSM>>>(3, 0, 96, in, OFF_W3p,  P(18), 2, 384, 128);
    k_tgemm<384, 256><<<g2, 256, DSM>>>(3, 2, 0,  in, OFF_W3_0, P(20), 1, 256, 0);
    // final head
    k_final<<<NB / 8, 256>>>(in, P(21), P(22), out);
}

// round 5
// speedup vs baseline: 3.3411x; 1.1075x over previous
#include <cuda_runtime.h>
#include <cuda_fp16.h>
#include <cstdint>

#define NB 65536

// ============================ device scratch ============================
__device__ int g_cnt[16];
__device__ int g_gidx[16][NB];
__device__ __align__(16) float g_h[(size_t)NB * 256];
__device__ __align__(16) float g_bufA[(size_t)NB * 384];
__device__ __align__(16) float g_bufB[(size_t)NB * 384];
// fp16 hi/lo weight planes, n-major [e][n][k], hi plane then lo plane per layer
__device__ __align__(16) __half g_wprep[3407872];

// layer offsets into g_wprep (half units)
static const size_t OFF_W0_0 = 0;
static const size_t OFF_W0_1 = 65536;
static const size_t OFF_W1p  = 327680;
static const size_t OFF_W1_0 = 393216;
static const size_t OFF_W1_1 = 1179648;
static const size_t OFF_W2p  = 1441792;
static const size_t OFF_W2_0 = 1507328;
static const size_t OFF_W2_1 = 2293760;
static const size_t OFF_W3p  = 2555904;
static const size_t OFF_W3_0 = 2621440;

// ============================ routing ============================
__global__ void k_zero() { if (threadIdx.x < 16) g_cnt[threadIdx.x] = 0; }

__global__ void k_route(const float* __restrict__ in) {
    int row = blockIdx.x * 256 + threadIdx.x;
    if (row >= NB) return;
    int lane = threadIdx.x & 31;
    const float* oh = in + (size_t)row * 144 + 128;
    #pragma unroll
    for (int j = 0; j < 4; j++) {
        int e = 0;
        #pragma unroll
        for (int t = 1; t < 4; t++) if (oh[j * 4 + t] > 0.5f) e = t;
        #pragma unroll
        for (int ee = 0; ee < 4; ee++) {
            unsigned m = __ballot_sync(0xffffffffu, e == ee);
            if (e == ee) {
                int leader = __ffs(m) - 1, base = 0;
                if (lane == leader) base = atomicAdd(&g_cnt[j * 4 + ee], __popc(m));
                base = __shfl_sync(m, base, leader);
                g_gidx[j * 4 + ee][base + __popc(m & ((1u << lane) - 1u))] = row;
            }
        }
    }
}

// ============================ fused weight prep ============================
// All 10 layers in one kernel. W [E][IN][OUT] fp32 -> hi/lo fp16 planes,
// n-major: plane[(e*OUT+n)*IN + k]
struct PrepArgs {
    const float* W[10];
};
__constant__ int c_in[10]   = {32, 256, 32, 384, 256, 32, 384, 256, 32, 384};
__constant__ int c_out[10]  = {256, 128, 256, 256, 128, 256, 256, 128, 256, 256};
__constant__ int c_cum[10]  = {0, 32768, 163840, 196608, 589824,
                               720896, 753664, 1146880, 1277952, 1310720};
__constant__ size_t c_base[10] = {OFF_W0_0, OFF_W0_1, OFF_W1p, OFF_W1_0, OFF_W1_1,
                                  OFF_W2p, OFF_W2_0, OFF_W2_1, OFF_W3p, OFF_W3_0};
#define PREP_TOTAL 1703936

__global__ void k_prep_all(PrepArgs pa) {
    for (int id = blockIdx.x * 256 + threadIdx.x; id < PREP_TOTAL; id += gridDim.x * 256) {
        int s = 9;
        #pragma unroll
        for (int i = 1; i < 10; i++) if (id < c_cum[i]) { s = i - 1; break; }
        int IN = c_in[s], OUT = c_out[s];
        int local = id - c_cum[s];
        int e = local / (OUT * IN);
        int rem = local % (OUT * IN);
        int n = rem / IN, k = rem % IN;
        float v = pa.W[s][((size_t)e * IN + k) * OUT + n];
        __half h = __float2half_rn(v);
        __half l = __float2half_rn(v - __half2float(h));
        size_t o = (size_t)(e * OUT + n) * IN + k;
        g_wprep[c_base[s] + o] = h;
        g_wprep[c_base[s] + (size_t)4 * OUT * IN + o] = l;
    }
}

// ============================ mma / ldmatrix helpers ============================
#define MMA16816(c, a, b) \
    asm volatile("mma.sync.aligned.m16n8k16.row.col.f32.f16.f16.f32 " \
        "{%0,%1,%2,%3}, {%4,%5,%6,%7}, {%8,%9}, {%0,%1,%2,%3};" \
        : "+f"((c)[0]), "+f"((c)[1]), "+f"((c)[2]), "+f"((c)[3]) \
        : "r"((a)[0]), "r"((a)[1]), "r"((a)[2]), "r"((a)[3]), \
          "r"((b)[0]), "r"((b)[1]))

#define LDSM_X4(r0, r1, r2, r3, addr) \
    asm volatile("ldmatrix.sync.aligned.m8n8.x4.shared.b16 {%0,%1,%2,%3}, [%4];" \
        : "=r"(r0), "=r"(r1), "=r"(r2), "=r"(r3) : "r"(addr))

__device__ __forceinline__ uint32_t smem_u32(const void* p) {
    return (uint32_t)__cvta_generic_to_shared(p);
}

// ============================ tensor GEMM ============================
// Block: 128 gathered rows x 128 cols (blockIdx.y = col block).
// K-extended split: A chunk cols [Ah | Al | Ah], B chunk cols [Bh | Bh | Bl]
// => fp32-accurate product via 3 fused fp16 passes. BK=32 -> 96 ext cols.
template <int IN, int OUT>
__global__ __launch_bounds__(256) void k_tgemm(
        int node, int asel, int acol, const float* __restrict__ fin,
        size_t woff, const float* __restrict__ Ball,
        int csel, int ldc, int ccol) {
    constexpr int SA = 104;          // padded row stride (halfs); conflict-free for LDSM
    constexpr int NCH = IN / 32;

    extern __shared__ __half dyn[];
    __half* sA = dyn;                // 128 x 104
    __half* sB = dyn + 128 * SA;     // 128 x 104
    __shared__ int s_ridx[128];
    __shared__ float s_bias[128];

    const int tid = threadIdx.x;
    const int cb = blockIdx.y;

    // map blockIdx.x -> (expert, tile)
    int e = -1, tile = 0, nrows = 0, acc0 = 0;
    #pragma unroll
    for (int ee = 0; ee < 4; ee++) {
        int ne = g_cnt[node * 4 + ee];
        int nt = (ne + 127) >> 7;
        if (e < 0 && (int)blockIdx.x < acc0 + nt) { e = ee; tile = (int)blockIdx.x - acc0; nrows = ne; }
        acc0 += nt;
    }
    if (e < 0) return;

    if (tid < 128) {
        int r = tile * 128 + tid;
        s_ridx[tid] = (r < nrows) ? g_gidx[node * 4 + e][r] : -1;
        s_bias[tid] = Ball[(size_t)e * OUT + cb * 128 + tid];
    }
    __syncthreads();

    const float* Aptr; int lda;
    if (asel == 0)      { Aptr = fin;    lda = 144; }
    else if (asel == 1) { Aptr = g_h;    lda = 256; }
    else if (asel == 2) { Aptr = g_bufA; lda = 384; }
    else                { Aptr = g_bufB; lda = 384; }
    float* C = (csel == 1) ? g_h : (csel == 2 ? g_bufA : g_bufB);

    const __half* wh = g_wprep + woff;
    const __half* wl = wh + (size_t)4 * OUT * IN;

    // staging assignment: thread -> row ar (0..127), half-chunk ak0 (0 or 16)
    const int ar = tid >> 1, ak0 = (tid & 1) * 16;
    const int ari = s_ridx[ar];
    const float* abase = Aptr + (size_t)(ari < 0 ? 0 : ari) * lda + acol + ak0;
    const __half* bhb = wh + ((size_t)(e * OUT + cb * 128 + ar) * IN + ak0);
    const __half* blb = wl + ((size_t)(e * OUT + cb * 128 + ar) * IN + ak0);

    float4 fA[4];
    uint4 bhv[2], blv[2];

    auto ldA = [&](int kk) {
        if (ari >= 0) {
            const float4* p = (const float4*)(abase + kk);
            fA[0] = p[0]; fA[1] = p[1]; fA[2] = p[2]; fA[3] = p[3];
        } else {
            fA[0] = fA[1] = fA[2] = fA[3] = make_float4(0.f, 0.f, 0.f, 0.f);
        }
    };
    auto ldB = [&](int kk) {
        const uint4* ph = (const uint4*)(bhb + kk);
        const uint4* pl = (const uint4*)(blb + kk);
        bhv[0] = ph[0]; bhv[1] = ph[1]; blv[0] = pl[0]; blv[1] = pl[1];
    };
    auto stA = [&]() {
        float v[16] = { fA[0].x, fA[0].y, fA[0].z, fA[0].w,
                        fA[1].x, fA[1].y, fA[1].z, fA[1].w,
                        fA[2].x, fA[2].y, fA[2].z, fA[2].w,
                        fA[3].x, fA[3].y, fA[3].z, fA[3].w };
        unsigned H[8], L[8];
        #pragma unroll
        for (int p = 0; p < 8; p++) {
            float v0 = v[2 * p], v1 = v[2 * p + 1];
            __half h0 = __float2half_rn(v0), h1 = __float2half_rn(v1);
            __half l0 = __float2half_rn(v0 - __half2float(h0));
            __half l1 = __float2half_rn(v1 - __half2float(h1));
            H[p] = ((unsigned)__half_as_ushort(h1) << 16) | __half_as_ushort(h0);
            L[p] = ((unsigned)__half_as_ushort(l1) << 16) | __half_as_ushort(l0);
        }
        uint4 h0 = make_uint4(H[0], H[1], H[2], H[3]);
        uint4 h1 = make_uint4(H[4], H[5], H[6], H[7]);
        uint4 l0 = make_uint4(L[0], L[1], L[2], L[3]);
        uint4 l1 = make_uint4(L[4], L[5], L[6], L[7]);
        __half* r = sA + ar * SA;
        *(uint4*)(r + ak0)          = h0; *(uint4*)(r + ak0 + 8)      = h1;   // Ah
        *(uint4*)(r + 32 + ak0)     = l0; *(uint4*)(r + 32 + ak0 + 8) = l1;   // Al
        *(uint4*)(r + 64 + ak0)     = h0; *(uint4*)(r + 64 + ak0 + 8) = h1;   // Ah
    };
    auto stB = [&]() {
        __half* r = sB + ar * SA;
        *(uint4*)(r + ak0)          = bhv[0]; *(uint4*)(r + ak0 + 8)      = bhv[1]; // Bh
        *(uint4*)(r + 32 + ak0)     = bhv[0]; *(uint4*)(r + 32 + ak0 + 8) = bhv[1]; // Bh
        *(uint4*)(r + 64 + ak0)     = blv[0]; *(uint4*)(r + 64 + ak0 + 8) = blv[1]; // Bl
    };

    // warp layout: 4 (m) x 2 (n); warp tile 32 rows x 64 cols
    const int w = tid >> 5, lane = tid & 31;
    const int m0 = (w >> 1) * 32, n0 = (w & 1) * 64;
    const int g = lane >> 2, t4 = lane & 3;
    const int q = lane >> 3;                 // ldmatrix quadrant 0..3

    // ldmatrix per-thread base addresses (halfs -> bytes x2)
    // A quad q: row += (lane&7) + (q&1)*8 ; col += (q>>1)*8
    uint32_t aAddr[2];
    #pragma unroll
    for (int ms = 0; ms < 2; ms++)
        aAddr[ms] = smem_u32(sA + (m0 + ms * 16 + (lane & 7) + (q & 1) * 8) * SA
                                 + (q >> 1) * 8);
    // B quad q: n row = n0 + (2j + (q>>1))*8 + (lane&7) ; col += (q&1)*8
    uint32_t bAddr[4];
    #pragma unroll
    for (int j = 0; j < 4; j++)
        bAddr[j] = smem_u32(sB + (n0 + (2 * j + (q >> 1)) * 8 + (lane & 7)) * SA
                                 + (q & 1) * 8);

    float acc[2][8][4];
    #pragma unroll
    for (int i = 0; i < 2; i++)
        #pragma unroll
        for (int j = 0; j < 8; j++)
            #pragma unroll
            for (int c = 0; c < 4; c++) acc[i][j][c] = 0.f;

    ldA(0); ldB(0);
    for (int ch = 0; ch < NCH; ch++) {
        stA(); stB();
        if (ch + 1 < NCH) { ldA((ch + 1) * 32); ldB((ch + 1) * 32); }
        __syncthreads();
        #pragma unroll
        for (int ks = 0; ks < 6; ks++) {
            const uint32_t kbb = ks * 32;     // 16 halfs = 32 bytes
            unsigned a[2][4], b[8][2];
            #pragma unroll
            for (int ms = 0; ms < 2; ms++)
                LDSM_X4(a[ms][0], a[ms][1], a[ms][2], a[ms][3], aAddr[ms] + kbb);
            #pragma unroll
            for (int j = 0; j < 4; j++)
                LDSM_X4(b[2 * j][0], b[2 * j][1], b[2 * j + 1][0], b[2 * j + 1][1],
                        bAddr[j] + kbb);
            #pragma unroll
            for (int ms = 0; ms < 2; ms++)
                #pragma unroll
                for (int ns = 0; ns < 8; ns++)
                    MMA16816(acc[ms][ns], a[ms], b[ns]);
        }
        __syncthreads();
    }

    // epilogue: bias + relu, scatter fp32
    #pragma unroll
    for (int ms = 0; ms < 2; ms++) {
        int r0 = m0 + ms * 16 + g;
        int ri = s_ridx[r0], rj = s_ridx[r0 + 8];
        float* c0p = C + (size_t)(ri < 0 ? 0 : ri) * ldc + ccol + cb * 128;
        float* c1p = C + (size_t)(rj < 0 ? 0 : rj) * ldc + ccol + cb * 128;
        #pragma unroll
        for (int ns = 0; ns < 8; ns++) {
            int cc = n0 + ns * 8 + 2 * t4;
            float b0 = s_bias[cc], b1 = s_bias[cc + 1];
            if (ri >= 0) {
                float2 v = make_float2(fmaxf(acc[ms][ns][0] + b0, 0.f),
                                       fmaxf(acc[ms][ns][1] + b1, 0.f));
                *(float2*)(c0p + cc) = v;
            }
            if (rj >= 0) {
                float2 v = make_float2(fmaxf(acc[ms][ns][2] + b0, 0.f),
                                       fmaxf(acc[ms][ns][3] + b1, 0.f));
                *(float2*)(c1p + cc) = v;
            }
        }
    }
}

// ============================ final 256->8 head (no relu) ============================
__global__ __launch_bounds__(256) void k_final(
        const float* __restrict__ in, const float* __restrict__ W,
        const float* __restrict__ Bb, float* __restrict__ out) {
    int gw = (blockIdx.x * 256 + threadIdx.x) >> 5;
    int lane = threadIdx.x & 31;
    if (gw >= NB) return;
    const float* oh = in + (size_t)gw * 144 + 140;
    int e = 0;
    #pragma unroll
    for (int t = 1; t < 4; t++) if (oh[t] > 0.5f) e = t;
    const float* h = g_h + (size_t)gw * 256;
    const float* w = W + (size_t)e * 2048;
    float acc[8] = {0, 0, 0, 0, 0, 0, 0, 0};
    #pragma unroll
    for (int kk = 0; kk < 256; kk += 32) {
        int k = kk + lane;
        float hv = h[k];
        float4 wa = *(const float4*)(w + k * 8);
        float4 wb = *(const float4*)(w + k * 8 + 4);
        acc[0] += hv * wa.x; acc[1] += hv * wa.y; acc[2] += hv * wa.z; acc[3] += hv * wa.w;
        acc[4] += hv * wb.x; acc[5] += hv * wb.y; acc[6] += hv * wb.z; acc[7] += hv * wb.w;
    }
    #pragma unroll
    for (int o = 16; o > 0; o >>= 1)
        #pragma unroll
        for (int c = 0; c < 8; c++) acc[c] += __shfl_xor_sync(0xffffffffu, acc[c], o);
    if (lane < 8) {
        float v = acc[0];
        switch (lane) {
            case 1: v = acc[1]; break; case 2: v = acc[2]; break;
            case 3: v = acc[3]; break; case 4: v = acc[4]; break;
            case 5: v = acc[5]; break; case 6: v = acc[6]; break;
            case 7: v = acc[7]; break; default: break;
        }
        out[(size_t)gw * 8 + lane] = v + Bb[e * 8 + lane];
    }
}

// ============================ launch ============================
extern "C" void kernel_launch(void* const* d_in, const int* in_sizes, int n_in,
                              void* d_out, int out_size) {
    const float* in = (const float*)d_in[0];
    float* out = (float*)d_out;
    auto P = [&](int i) { return (const float*)d_in[i]; };

    const int DSM = 256 * 104 * 2;  // 53248 B
    cudaFuncSetAttribute((const void*)k_tgemm<32, 256>,
                         cudaFuncAttributeMaxDynamicSharedMemorySize, DSM);
    cudaFuncSetAttribute((const void*)k_tgemm<256, 128>,
                         cudaFuncAttributeMaxDynamicSharedMemorySize, DSM);
    cudaFuncSetAttribute((const void*)k_tgemm<384, 256>,
                         cudaFuncAttributeMaxDynamicSharedMemorySize, DSM);

    PrepArgs pa;
    pa.W[0] = P(1);  pa.W[1] = P(3);  pa.W[2] = P(5);  pa.W[3] = P(7);  pa.W[4] = P(9);
    pa.W[5] = P(11); pa.W[6] = P(13); pa.W[7] = P(15); pa.W[8] = P(17); pa.W[9] = P(19);
    k_prep_all<<<1024, 256>>>(pa);

    k_zero<<<1, 16>>>();
    k_route<<<NB / 256, 256>>>(in);

    dim3 g2(516, 2), g1(516, 1);
    // node 0
    k_tgemm<32, 256><<<g2, 256, DSM>>>(0, 0, 0,  in, OFF_W0_0, P(2),  1, 256, 0);
    k_tgemm<256, 128><<<g1, 256, DSM>>>(0, 1, 0,  in, OFF_W0_1, P(4),  2, 384, 0);
    // node 1
    k_tgemm<32, 256><<<g2, 256, DSM>>>(1, 0, 32, in, OFF_W1p,  P(6),  2, 384, 128);
    k_tgemm<384, 256><<<g2, 256, DSM>>>(1, 2, 0,  in, OFF_W1_0, P(8),  1, 256, 0);
    k_tgemm<256, 128><<<g1, 256, DSM>>>(1, 1, 0,  in, OFF_W1_1, P(10), 3, 384, 0);
    // node 2
    k_tgemm<32, 256><<<g2, 256, DSM>>>(2, 0, 64, in, OFF_W2p,  P(12), 3, 384, 128);
    k_tgemm<384, 256><<<g2, 256, DSM>>>(2, 3, 0,  in, OFF_W2_0, P(14), 1, 256, 0);
    k_tgemm<256, 128><<<g1, 256, DSM>>>(2, 1, 0,  in, OFF_W2_1, P(16), 2, 384, 0);
    // node 3
    k_tgemm<32, 256><<<g2, 256, DSM>>>(3, 0, 96, in, OFF_W3p,  P(18), 2, 384, 128);
    k_tgemm<384, 256><<<g2, 256, DSM>>>(3, 2, 0,  in, OFF_W3_0, P(20), 1, 256, 0);
    // final head
    k_final<<<NB / 8, 256>>>(in, P(21), P(22), out);
}